// round 12
// baseline (speedup 1.0000x reference)
#include <cuda_runtime.h>
#include <cuda_bf16.h>
#include <cstdint>

#define BATCH   8192
#define DIM     1024
#define NCLASS  1000
#define CPAD    1024
#define N_PAIRS 499500.0f   // 1000*999/2
#define BUCKET_CAP 64

// ---------------- scratch (device globals; zero at load) ----------------
__device__ int   g_counts[CPAD];               // zeroed by k_fused final block
__device__ int   g_bucket[NCLASS * BUCKET_CAP];
__device__ int   g_ovf[BATCH];                 // overflow (class<<16 | row)
__device__ int   g_novf;                       // zeroed by k_fused final block
__device__ float g_centers_new[CPAD * DIM];           // rows >= NCLASS stay 0
__device__ __nv_bfloat16 g_centers_bf16[CPAD * DIM];  // rows >= NCLASS stay 0
__device__ float g_sq[CPAD];                          // entries >= NCLASS stay 0
__device__ float g_accum[2];                   // zeroed by k_fused final block
__device__ int   g_done;                       // zeroed by k_fused final block

// ---------------- helpers ----------------
__device__ __forceinline__ int probe_lab64_block(const int* w, int t, int* s_flag) {
    if (t < 32) {
        unsigned nz = __ballot_sync(0xffffffffu, w[2 * t + 1] != 0);
        if (t == 0) *s_flag = (nz == 0u);
    }
    __syncthreads();
    return *s_flag;
}

__device__ __forceinline__ int decode_label(const int* w, int b, int lab64) {
    int v = lab64 ? w[2 * b] : w[b];
    return (v >= 0 && v < NCLASS) ? v : 0;
}

__device__ __forceinline__ float warp_sum(float v) {
    #pragma unroll
    for (int o = 16; o; o >>= 1) v += __shfl_xor_sync(0xffffffffu, v, o);
    return v;
}

__device__ __forceinline__ void ldsm_x4(uint32_t r[4], uint32_t saddr) {
    asm volatile("ldmatrix.sync.aligned.m8n8.x4.shared.b16 {%0,%1,%2,%3}, [%4];"
                 : "=r"(r[0]), "=r"(r[1]), "=r"(r[2]), "=r"(r[3]) : "r"(saddr));
}

__device__ __forceinline__ void mma16816(float d[4], const uint32_t a[4], uint32_t b0, uint32_t b1) {
    asm volatile("mma.sync.aligned.m16n8k16.row.col.f32.bf16.bf16.f32 "
                 "{%0,%1,%2,%3},{%4,%5,%6,%7},{%8,%9},{%0,%1,%2,%3};"
                 : "+f"(d[0]), "+f"(d[1]), "+f"(d[2]), "+f"(d[3])
                 : "r"(a[0]), "r"(a[1]), "r"(a[2]), "r"(a[3]), "r"(b0), "r"(b1));
}

__device__ __forceinline__ void cp_async16(uint32_t saddr, const void* gaddr) {
    asm volatile("cp.async.cg.shared.global [%0], [%1], 16;" :: "r"(saddr), "l"(gaddr));
}
__device__ __forceinline__ void cp_commit()  { asm volatile("cp.async.commit_group;"); }
__device__ __forceinline__ void cp_wait0()   { asm volatile("cp.async.wait_group 0;"); }
__device__ __forceinline__ void cp_wait1()   { asm volatile("cp.async.wait_group 1;"); }

// ============ 1: bucket scatter — no scan, no grid barrier ============
__global__ __launch_bounds__(256) void k_prep(const void* __restrict__ labels) {
    __shared__ int s_lab64;
    int t = threadIdx.x;
    const int* w = (const int*)labels;
    int lab64 = probe_lab64_block(w, t, &s_lab64);

    int b = blockIdx.x * 256 + t;   // 32 blocks * 256 = BATCH
    int lab = decode_label(w, b, lab64);
    int pos = atomicAdd(&g_counts[lab], 1);
    if (pos < BUCKET_CAP) {
        g_bucket[lab * BUCKET_CAP + pos] = b;
    } else {
        int o = atomicAdd(&g_novf, 1);
        if (o < BATCH) g_ovf[o] = (lab << 16) | b;
    }
}

// ============ 2: center update — warp-per-row inline norms, smem-atomic accumulate ============
__global__ __launch_bounds__(256) void k_update(const float* __restrict__ f,
                                                const float* __restrict__ centers) {
    __shared__ float s_acc[DIM];   // 4 KB class accumulator
    __shared__ float red[8];

    int c = blockIdx.x;
    int t = threadIdx.x;
    int wid = t >> 5, lane = t & 31;
    int cnt = g_counts[c];
    int inb = min(cnt, BUCKET_CAP);

    *(float4*)&s_acc[t * 4] = make_float4(0.f, 0.f, 0.f, 0.f);
    __syncthreads();

    for (int i = wid; i < inb; i += 8) {
        int r = g_bucket[c * BUCKET_CAP + i];
        const float4* row = (const float4*)(f + (size_t)r * DIM);
        float4 v[8];
        float ss = 0.f;
        #pragma unroll
        for (int q = 0; q < 8; q++) {
            v[q] = row[q * 32 + lane];
            ss += v[q].x * v[q].x + v[q].y * v[q].y + v[q].z * v[q].z + v[q].w * v[q].w;
        }
        ss = warp_sum(ss);
        float inv = 1.0f / fmaxf(sqrtf(ss), 1e-12f);
        #pragma unroll
        for (int q = 0; q < 8; q++) {
            float* dst = &s_acc[q * 128 + lane * 4];   // conflict-free across lanes
            atomicAdd(dst + 0, v[q].x * inv);
            atomicAdd(dst + 1, v[q].y * inv);
            atomicAdd(dst + 2, v[q].z * inv);
            atomicAdd(dst + 3, v[q].w * inv);
        }
    }

    int novf = min(g_novf, BATCH);
    for (int i = wid; i < novf; i += 8) {
        int e = g_ovf[i];
        if ((e >> 16) == c) {
            int r = e & 0xffff;
            const float4* row = (const float4*)(f + (size_t)r * DIM);
            float4 v[8];
            float ss = 0.f;
            #pragma unroll
            for (int q = 0; q < 8; q++) {
                v[q] = row[q * 32 + lane];
                ss += v[q].x * v[q].x + v[q].y * v[q].y + v[q].z * v[q].z + v[q].w * v[q].w;
            }
            ss = warp_sum(ss);
            float inv = 1.0f / fmaxf(sqrtf(ss), 1e-12f);
            #pragma unroll
            for (int q = 0; q < 8; q++) {
                float* dst = &s_acc[q * 128 + lane * 4];
                atomicAdd(dst + 0, v[q].x * inv);
                atomicAdd(dst + 1, v[q].y * inv);
                atomicAdd(dst + 2, v[q].z * inv);
                atomicAdd(dst + 3, v[q].w * inv);
            }
        }
    }
    __syncthreads();

    float4 sum = *(float4*)&s_acc[t * 4];
    float rc = 1.0f / fmaxf((float)cnt, 1.0f);
    float4 mean = {sum.x * rc, sum.y * rc, sum.z * rc, sum.w * rc};
    float4 co = *(const float4*)(centers + (size_t)c * DIM + t * 4);

    int zflag = (co.x == 0.f && co.y == 0.f && co.z == 0.f && co.w == 0.f);
    int allz = __syncthreads_and(zflag);

    float4 outv;
    if (cnt > 0) {
        if (allz) outv = mean;
        else {
            outv.x = 0.9f * co.x + 0.1f * mean.x;
            outv.y = 0.9f * co.y + 0.1f * mean.y;
            outv.z = 0.9f * co.z + 0.1f * mean.z;
            outv.w = 0.9f * co.w + 0.1f * mean.w;
        }
    } else outv = co;

    *(float4*)(g_centers_new + (size_t)c * DIM + t * 4) = outv;

    __nv_bfloat162 p0 = __floats2bfloat162_rn(outv.x, outv.y);
    __nv_bfloat162 p1 = __floats2bfloat162_rn(outv.z, outv.w);
    uint2 pk;
    pk.x = *(uint32_t*)&p0;
    pk.y = *(uint32_t*)&p1;
    *(uint2*)(g_centers_bf16 + (size_t)c * DIM + t * 4) = pk;

    float s = outv.x * outv.x + outv.y * outv.y + outv.z * outv.z + outv.w * outv.w;
    s = warp_sum(s);
    if ((t & 31) == 0) red[t >> 5] = s;
    __syncthreads();
    if (t == 0) {
        float tot = 0.f;
        #pragma unroll
        for (int q = 0; q < 8; q++) tot += red[q];
        g_sq[c] = tot;
    }
}

// ============ 3: fused GEMM-first + intra + final/reset, 4 blocks/SM ============
#define GEMM_BLOCKS  72
#define INTRA_BLOCKS 1024
#define KTILE 32
#define RSTRIDE 80                  // 32 bf16 = 64 B + 16 B pad (odd # of 16B units)
#define BUFB (192 * RSTRIDE)        // 15360 B per stage
#define FUSED_SMEM 32768            // union: GEMM 2*15360=30720 | intra 8 warps * 4KB

__global__ __launch_bounds__(256, 4) void k_fused(const float* __restrict__ f,
                                                  const float* __restrict__ fa,
                                                  const void* __restrict__ labels,
                                                  float* __restrict__ out) {
    __shared__ __align__(16) char s_raw[FUSED_SMEM];
    __shared__ int s_amlast;

    int t = threadIdx.x;
    int wid = t >> 5, lane = t & 31;
    uint32_t sbase = (uint32_t)__cvta_generic_to_shared(s_raw);

    if (blockIdx.x >= GEMM_BLOCKS) {
        // -------- intra: f staged in regs, fa streamed via cp.async (lane-private) --------
        __shared__ int s_lab64;
        const int* w = (const int*)labels;
        int lab64 = probe_lab64_block(w, t, &s_lab64);

        int b = (blockIdx.x - GEMM_BLOCKS) * 8 + wid;
        int lab = decode_label(w, b, lab64);

        const float4* fr  = (const float4*)(f  + (size_t)b * DIM);
        const float4* far = (const float4*)(fa + (size_t)b * DIM);
        const float4* cr  = (const float4*)(g_centers_new + (size_t)lab * DIM);

        // fa row -> smem: each lane copies exactly the chunks it will read back
        uint32_t mybase = sbase + wid * 4096;
        #pragma unroll
        for (int q = 0; q < 8; q++)
            cp_async16(mybase + (q * 32 + lane) * 16, &far[q * 32 + lane]);
        cp_commit();

        // f row staged in registers (16-deep with the cp.asyncs above)
        float4 v[8];
        #pragma unroll
        for (int q = 0; q < 8; q++) v[q] = fr[q * 32 + lane];

        float df = 0.f, ssf = 0.f;
        #pragma unroll
        for (int q = 0; q < 8; q++) {
            float4 cv = cr[q * 32 + lane];
            df  += v[q].x * cv.x + v[q].y * cv.y + v[q].z * cv.z + v[q].w * cv.w;
            ssf += v[q].x * v[q].x + v[q].y * v[q].y + v[q].z * v[q].z + v[q].w * v[q].w;
        }

        cp_wait0();   // own chunks visible to own lane
        float dfa = 0.f, ssa = 0.f;
        #pragma unroll
        for (int q = 0; q < 8; q++) {
            float4 a = *(float4*)(s_raw + wid * 4096 + (q * 32 + lane) * 16);
            float4 cv = cr[q * 32 + lane];   // L1-hot reload
            dfa += a.x * cv.x + a.y * cv.y + a.z * cv.z + a.w * cv.w;
            ssa += a.x * a.x + a.y * a.y + a.z * a.z + a.w * a.w;
        }

        df  = warp_sum(df);
        dfa = warp_sum(dfa);
        ssf = warp_sum(ssf);
        ssa = warp_sum(ssa);

        float* bsum = (float*)s_raw;    // t0 writes only its own (already-consumed) bytes
        if (t == 0) *bsum = 0.f;
        __syncthreads();
        if (lane == 0) {
            float invf  = 1.0f / fmaxf(sqrtf(ssf), 1e-12f);
            float invfa = 1.0f / fmaxf(sqrtf(ssa), 1e-12f);
            float sqc = g_sq[lab];
            float d1 = sqrtf(fmaxf(1.0f - 2.0f * df  * invf  + sqc, 0.0f));
            float d2 = sqrtf(fmaxf(1.0f - 2.0f * dfa * invfa + sqc, 0.0f));
            atomicAdd(bsum, d1 + d2);
        }
        __syncthreads();
        if (t == 0) atomicAdd(&g_accum[0], *bsum);
    } else {
        // -------- bf16 GEMM, KTILE=32, 2-stage cp.async pipeline --------
        int rem = blockIdx.x, ti = 0;
        while (rem >= 16 - 2 * ti) { rem -= 16 - 2 * ti; ti++; }
        int tj = 2 * ti + rem;
        int ibase = ti * 128, jbase = tj * 64;

        int m0 = (wid & 3) * 32;
        int n0 = (wid >> 2) * 32;

        // chunk map: 192 rows * 4 chunks = 768; slot = t + 256*s
        const __nv_bfloat16* gsrc[3];
        uint32_t sdst[3];
        #pragma unroll
        for (int s = 0; s < 3; s++) {
            int slot = t + s * 256;
            int row = slot >> 2, c16 = slot & 3;
            int grow = (row < 128) ? (ibase + row) : (jbase + row - 128);
            gsrc[s] = g_centers_bf16 + (size_t)grow * DIM + c16 * 8;
            sdst[s] = sbase + row * RSTRIDE + c16 * 16;
        }

        // prologue: tiles 0 and 1
        #pragma unroll
        for (int s = 0; s < 3; s++) cp_async16(sdst[s], gsrc[s]);
        cp_commit();
        #pragma unroll
        for (int s = 0; s < 3; s++) cp_async16(sdst[s] + BUFB, gsrc[s] + KTILE);
        cp_commit();

        float acc[2][4][4] = {};
        int lr = lane & 15, lc = lane >> 4;

        for (int it = 0; it < 32; it++) {
            if (it < 31) cp_wait1(); else cp_wait0();
            __syncthreads();

            uint32_t buf = sbase + (it & 1) * BUFB;
            uint32_t abase = buf + (m0 + lr) * RSTRIDE + lc * 16;
            uint32_t bbase = buf + (128 + n0 + lr) * RSTRIDE + lc * 16;
            #pragma unroll
            for (int kk = 0; kk < 2; kk++) {
                uint32_t af[2][4], bf[2][4];
                ldsm_x4(af[0], abase + kk * 32);
                ldsm_x4(af[1], abase + kk * 32 + 16 * RSTRIDE);
                ldsm_x4(bf[0], bbase + kk * 32);
                ldsm_x4(bf[1], bbase + kk * 32 + 16 * RSTRIDE);

                #pragma unroll
                for (int mi = 0; mi < 2; mi++) {
                    #pragma unroll
                    for (int g = 0; g < 2; g++) {
                        mma16816(acc[mi][g * 2 + 0], af[mi], bf[g][0], bf[g][2]);
                        mma16816(acc[mi][g * 2 + 1], af[mi], bf[g][1], bf[g][3]);
                    }
                }
            }
            __syncthreads();
            if (it + 2 < 32) {
                #pragma unroll
                for (int s = 0; s < 3; s++)
                    cp_async16(sdst[s] + (it & 1) * BUFB, gsrc[s] + (it + 2) * KTILE);
                cp_commit();
            }
        }

        // epilogue: dist + relu reduction (mapping validated)
        float local = 0.f;
        int g8 = lane >> 2, tg = lane & 3;
        #pragma unroll
        for (int mi = 0; mi < 2; mi++) {
            #pragma unroll
            for (int nt = 0; nt < 4; nt++) {
                #pragma unroll
                for (int r = 0; r < 4; r++) {
                    int i = ibase + m0 + mi * 16 + g8 + ((r >> 1) * 8);
                    int j = jbase + n0 + nt * 8 + tg * 2 + (r & 1);
                    if (i < j && j < NCLASS) {
                        float d2 = g_sq[i] + g_sq[j] - 2.0f * acc[mi][nt][r];
                        float d  = sqrtf(fmaxf(d2, 0.0f));
                        local += fmaxf(1.0f - d, 0.0f);
                    }
                }
            }
        }
        local = warp_sum(local);
        float* ws = (float*)s_raw;
        __syncthreads();
        if (lane == 0) ws[wid] = local;
        __syncthreads();
        if (t == 0) {
            float tot = 0.f;
            #pragma unroll
            for (int q = 0; q < 8; q++) tot += ws[q];
            atomicAdd(&g_accum[1], tot);
        }
    }

    // -------- last-block final output + state reset for next replay --------
    __threadfence();
    __syncthreads();
    if (t == 0) {
        int d = atomicAdd(&g_done, 1);
        s_amlast = (d == (int)gridDim.x - 1);
    }
    __syncthreads();
    if (s_amlast) {
        if (t == 0) {
            float intra = g_accum[0] / (float)BATCH;
            float inter = g_accum[1] / N_PAIRS;
            out[0] = intra - 0.5f * inter;
            g_accum[0] = 0.f;
            g_accum[1] = 0.f;
            g_novf = 0;
            g_done = 0;
        }
        #pragma unroll
        for (int q = 0; q < 4; q++) g_counts[t + q * 256] = 0;
    }
}

// ---------------- launch ----------------
extern "C" void kernel_launch(void* const* d_in, const int* in_sizes, int n_in,
                              void* d_out, int out_size) {
    const float* f       = (const float*)d_in[0];
    const float* fa      = (const float*)d_in[1];
    const float* centers = (const float*)d_in[2];
    const void*  labels  = d_in[3];
    float* out = (float*)d_out;

    k_prep<<<BATCH / 256, 256>>>(labels);
    k_update<<<NCLASS, 256>>>(f, centers);
    k_fused<<<GEMM_BLOCKS + INTRA_BLOCKS, 256>>>(f, fa, labels, out);
}

// round 13
// speedup vs baseline: 1.0735x; 1.0735x over previous
#include <cuda_runtime.h>
#include <cuda_bf16.h>
#include <cstdint>

#define BATCH   8192
#define DIM     1024
#define NCLASS  1000
#define CPAD    1024
#define N_PAIRS 499500.0f   // 1000*999/2
#define BUCKET_CAP 64

// ---------------- scratch (device globals; zero at load) ----------------
__device__ int   g_counts[CPAD];               // zeroed by k_fused final block
__device__ int   g_bucket[NCLASS * BUCKET_CAP];
__device__ int   g_ovf[BATCH];                 // overflow (class<<16 | row)
__device__ int   g_novf;                       // zeroed by k_fused final block
__device__ float g_centers_new[CPAD * DIM];           // rows >= NCLASS stay 0
__device__ __nv_bfloat16 g_centers_bf16[CPAD * DIM];  // rows >= NCLASS stay 0
__device__ float g_sq[CPAD];                          // entries >= NCLASS stay 0
__device__ float g_accum[2];                   // zeroed by k_fused final block
__device__ int   g_done;                       // zeroed by k_fused final block

// ---------------- helpers ----------------
__device__ __forceinline__ int probe_lab64_block(const int* w, int t, int* s_flag) {
    if (t < 32) {
        unsigned nz = __ballot_sync(0xffffffffu, w[2 * t + 1] != 0);
        if (t == 0) *s_flag = (nz == 0u);
    }
    __syncthreads();
    return *s_flag;
}

__device__ __forceinline__ int decode_label(const int* w, int b, int lab64) {
    int v = lab64 ? w[2 * b] : w[b];
    return (v >= 0 && v < NCLASS) ? v : 0;
}

__device__ __forceinline__ float warp_sum(float v) {
    #pragma unroll
    for (int o = 16; o; o >>= 1) v += __shfl_xor_sync(0xffffffffu, v, o);
    return v;
}

__device__ __forceinline__ void ldsm_x4(uint32_t r[4], uint32_t saddr) {
    asm volatile("ldmatrix.sync.aligned.m8n8.x4.shared.b16 {%0,%1,%2,%3}, [%4];"
                 : "=r"(r[0]), "=r"(r[1]), "=r"(r[2]), "=r"(r[3]) : "r"(saddr));
}

__device__ __forceinline__ void mma16816(float d[4], const uint32_t a[4], uint32_t b0, uint32_t b1) {
    asm volatile("mma.sync.aligned.m16n8k16.row.col.f32.bf16.bf16.f32 "
                 "{%0,%1,%2,%3},{%4,%5,%6,%7},{%8,%9},{%0,%1,%2,%3};"
                 : "+f"(d[0]), "+f"(d[1]), "+f"(d[2]), "+f"(d[3])
                 : "r"(a[0]), "r"(a[1]), "r"(a[2]), "r"(a[3]), "r"(b0), "r"(b1));
}

// ============ 1: bucket scatter — no scan, no grid barrier ============
__global__ __launch_bounds__(256) void k_prep(const void* __restrict__ labels) {
    __shared__ int s_lab64;
    int t = threadIdx.x;
    const int* w = (const int*)labels;
    int lab64 = probe_lab64_block(w, t, &s_lab64);

    int b = blockIdx.x * 256 + t;   // 32 blocks * 256 = BATCH
    int lab = decode_label(w, b, lab64);
    int pos = atomicAdd(&g_counts[lab], 1);
    if (pos < BUCKET_CAP) {
        g_bucket[lab * BUCKET_CAP + pos] = b;
    } else {
        int o = atomicAdd(&g_novf, 1);
        if (o < BATCH) g_ovf[o] = (lab << 16) | b;
    }
}

// ============ 2: center update + fused intra-clean distance ============
__global__ __launch_bounds__(256) void k_update(const float* __restrict__ f,
                                                const float* __restrict__ centers) {
    __shared__ float s_acc[DIM];   // 4 KB: accumulator, then c_new for d1 pass
    __shared__ float red[8];
    __shared__ float s_sqc;
    __shared__ float s_dsum;

    int c = blockIdx.x;
    int t = threadIdx.x;
    int wid = t >> 5, lane = t & 31;
    int cnt = g_counts[c];
    int inb = min(cnt, BUCKET_CAP);
    int novf = min(g_novf, BATCH);

    *(float4*)&s_acc[t * 4] = make_float4(0.f, 0.f, 0.f, 0.f);
    if (t == 0) s_dsum = 0.f;
    __syncthreads();

    // ---- phase 1: accumulate normalized member rows (warp per row) ----
    for (int i = wid; i < inb; i += 8) {
        int r = g_bucket[c * BUCKET_CAP + i];
        const float4* row = (const float4*)(f + (size_t)r * DIM);
        float4 v[8];
        float ss = 0.f;
        #pragma unroll
        for (int q = 0; q < 8; q++) {
            v[q] = row[q * 32 + lane];
            ss += v[q].x * v[q].x + v[q].y * v[q].y + v[q].z * v[q].z + v[q].w * v[q].w;
        }
        ss = warp_sum(ss);
        float inv = 1.0f / fmaxf(sqrtf(ss), 1e-12f);
        #pragma unroll
        for (int q = 0; q < 8; q++) {
            float* dst = &s_acc[q * 128 + lane * 4];   // conflict-free across lanes
            atomicAdd(dst + 0, v[q].x * inv);
            atomicAdd(dst + 1, v[q].y * inv);
            atomicAdd(dst + 2, v[q].z * inv);
            atomicAdd(dst + 3, v[q].w * inv);
        }
    }
    for (int i = wid; i < novf; i += 8) {
        int e = g_ovf[i];
        if ((e >> 16) == c) {
            int r = e & 0xffff;
            const float4* row = (const float4*)(f + (size_t)r * DIM);
            float4 v[8];
            float ss = 0.f;
            #pragma unroll
            for (int q = 0; q < 8; q++) {
                v[q] = row[q * 32 + lane];
                ss += v[q].x * v[q].x + v[q].y * v[q].y + v[q].z * v[q].z + v[q].w * v[q].w;
            }
            ss = warp_sum(ss);
            float inv = 1.0f / fmaxf(sqrtf(ss), 1e-12f);
            #pragma unroll
            for (int q = 0; q < 8; q++) {
                float* dst = &s_acc[q * 128 + lane * 4];
                atomicAdd(dst + 0, v[q].x * inv);
                atomicAdd(dst + 1, v[q].y * inv);
                atomicAdd(dst + 2, v[q].z * inv);
                atomicAdd(dst + 3, v[q].w * inv);
            }
        }
    }
    __syncthreads();

    // ---- phase 2: momentum update, outputs ----
    float4 sum = *(float4*)&s_acc[t * 4];
    float rc = 1.0f / fmaxf((float)cnt, 1.0f);
    float4 mean = {sum.x * rc, sum.y * rc, sum.z * rc, sum.w * rc};
    float4 co = *(const float4*)(centers + (size_t)c * DIM + t * 4);

    int zflag = (co.x == 0.f && co.y == 0.f && co.z == 0.f && co.w == 0.f);
    int allz = __syncthreads_and(zflag);

    float4 outv;
    if (cnt > 0) {
        if (allz) outv = mean;
        else {
            outv.x = 0.9f * co.x + 0.1f * mean.x;
            outv.y = 0.9f * co.y + 0.1f * mean.y;
            outv.z = 0.9f * co.z + 0.1f * mean.z;
            outv.w = 0.9f * co.w + 0.1f * mean.w;
        }
    } else outv = co;

    *(float4*)(g_centers_new + (size_t)c * DIM + t * 4) = outv;

    __nv_bfloat162 p0 = __floats2bfloat162_rn(outv.x, outv.y);
    __nv_bfloat162 p1 = __floats2bfloat162_rn(outv.z, outv.w);
    uint2 pk;
    pk.x = *(uint32_t*)&p0;
    pk.y = *(uint32_t*)&p1;
    *(uint2*)(g_centers_bf16 + (size_t)c * DIM + t * 4) = pk;

    // park c_new in smem (allz barrier above ordered the phase-2 reads)
    *(float4*)&s_acc[t * 4] = outv;

    float s = outv.x * outv.x + outv.y * outv.y + outv.z * outv.z + outv.w * outv.w;
    s = warp_sum(s);
    if ((t & 31) == 0) red[t >> 5] = s;
    __syncthreads();
    if (t == 0) {
        float tot = 0.f;
        #pragma unroll
        for (int q = 0; q < 8; q++) tot += red[q];
        g_sq[c] = tot;
        s_sqc = tot;
    }
    __syncthreads();

    // ---- phase 3: intra-clean distances, warp per member (rows L2-hot) ----
    float sqc = s_sqc;
    float dsum = 0.f;
    for (int i = wid; i < inb; i += 8) {
        int r = g_bucket[c * BUCKET_CAP + i];
        const float4* row = (const float4*)(f + (size_t)r * DIM);
        float ss = 0.f, dot = 0.f;
        #pragma unroll
        for (int q = 0; q < 8; q++) {
            float4 v = row[q * 32 + lane];
            float4 cv = *(float4*)&s_acc[q * 128 + lane * 4];
            ss  += v.x * v.x + v.y * v.y + v.z * v.z + v.w * v.w;
            dot += v.x * cv.x + v.y * cv.y + v.z * cv.z + v.w * cv.w;
        }
        ss  = warp_sum(ss);
        dot = warp_sum(dot);
        if (lane == 0) {
            float inv = 1.0f / fmaxf(sqrtf(ss), 1e-12f);
            dsum += sqrtf(fmaxf(1.0f - 2.0f * dot * inv + sqc, 0.0f));
        }
    }
    for (int i = wid; i < novf; i += 8) {
        int e = g_ovf[i];
        if ((e >> 16) == c) {
            int r = e & 0xffff;
            const float4* row = (const float4*)(f + (size_t)r * DIM);
            float ss = 0.f, dot = 0.f;
            #pragma unroll
            for (int q = 0; q < 8; q++) {
                float4 v = row[q * 32 + lane];
                float4 cv = *(float4*)&s_acc[q * 128 + lane * 4];
                ss  += v.x * v.x + v.y * v.y + v.z * v.z + v.w * v.w;
                dot += v.x * cv.x + v.y * cv.y + v.z * cv.z + v.w * cv.w;
            }
            ss  = warp_sum(ss);
            dot = warp_sum(dot);
            if (lane == 0) {
                float inv = 1.0f / fmaxf(sqrtf(ss), 1e-12f);
                dsum += sqrtf(fmaxf(1.0f - 2.0f * dot * inv + sqc, 0.0f));
            }
        }
    }
    if (lane == 0 && dsum != 0.f) atomicAdd(&s_dsum, dsum);
    __syncthreads();
    if (t == 0 && s_dsum != 0.f) atomicAdd(&g_accum[0], s_dsum);
}

// ============ 3: fused GEMM-first + intra-adv + final/reset (R11-proven skeleton) ============
#define GEMM_BLOCKS  72
#define INTRA_BLOCKS 1024
#define KTILE 64
#define RSTRIDE 144                 // 64 bf16 = 128 B + 16 B pad (odd # of 16B units)
#define GEMM_SMEM (192 * RSTRIDE)   // A(128 rows) + B(64 rows): 27648 B

__global__ __launch_bounds__(256, 3) void k_fused(const float* __restrict__ fa,
                                                  const void* __restrict__ labels,
                                                  float* __restrict__ out) {
    __shared__ __align__(16) char s_raw[GEMM_SMEM];
    __shared__ int s_amlast;

    int t = threadIdx.x;
    int wid = t >> 5, lane = t & 31;

    if (blockIdx.x >= GEMM_BLOCKS) {
        // -------- intra-adv only: fa staged in regs, center from L2 --------
        __shared__ int s_lab64;
        const int* w = (const int*)labels;
        int lab64 = probe_lab64_block(w, t, &s_lab64);

        int b = (blockIdx.x - GEMM_BLOCKS) * 8 + wid;
        int lab = decode_label(w, b, lab64);

        const float4* far = (const float4*)(fa + (size_t)b * DIM);
        const float4* cr  = (const float4*)(g_centers_new + (size_t)lab * DIM);

        float4 va[8];
        #pragma unroll
        for (int q = 0; q < 8; q++) va[q] = far[q * 32 + lane];

        float dfa = 0.f, ssa = 0.f;
        #pragma unroll
        for (int q = 0; q < 8; q++) {
            float4 cv = cr[q * 32 + lane];
            dfa += va[q].x * cv.x + va[q].y * cv.y + va[q].z * cv.z + va[q].w * cv.w;
            ssa += va[q].x * va[q].x + va[q].y * va[q].y + va[q].z * va[q].z + va[q].w * va[q].w;
        }
        dfa = warp_sum(dfa);
        ssa = warp_sum(ssa);

        float* bsum = (float*)s_raw;
        if (t == 0) *bsum = 0.f;
        __syncthreads();
        if (lane == 0) {
            float invfa = 1.0f / fmaxf(sqrtf(ssa), 1e-12f);
            float sqc = g_sq[lab];
            float d2 = sqrtf(fmaxf(1.0f - 2.0f * dfa * invfa + sqc, 0.0f));
            atomicAdd(bsum, d2);
        }
        __syncthreads();
        if (t == 0) atomicAdd(&g_accum[0], *bsum);
    } else {
        // -------- bf16 GEMM, K-tile 64, register staging (R11 body) --------
        int rem = blockIdx.x, ti = 0;
        while (rem >= 16 - 2 * ti) { rem -= 16 - 2 * ti; ti++; }
        int tj = 2 * ti + rem;
        int ibase = ti * 128, jbase = tj * 64;

        int m0 = (wid & 3) * 32;
        int n0 = (wid >> 2) * 32;

        uint32_t sbase = (uint32_t)__cvta_generic_to_shared(s_raw);

        int goff[6], soff[6];
        #pragma unroll
        for (int s = 0; s < 6; s++) {
            int slot = t + s * 256;
            int row = slot >> 3, c16 = slot & 7;
            int grow = (row < 128) ? (ibase + row) : (jbase + row - 128);
            goff[s] = grow * DIM + c16 * 8;       // bf16 elements
            soff[s] = row * RSTRIDE + c16 * 16;   // bytes
        }

        #pragma unroll
        for (int s = 0; s < 6; s++) {
            uint4 val = *(const uint4*)(g_centers_bf16 + goff[s]);
            *(uint4*)(s_raw + soff[s]) = val;
        }
        __syncthreads();

        float acc[2][4][4] = {};
        int lr = lane & 15, lc = lane >> 4;
        uint32_t abase0 = sbase + (m0 + lr) * RSTRIDE + lc * 16;
        uint32_t bbase0 = sbase + (128 + n0 + lr) * RSTRIDE + lc * 16;

        for (int it = 0; it < 16; it++) {
            uint4 stg[6];
            if (it < 15) {
                #pragma unroll
                for (int s = 0; s < 6; s++)
                    stg[s] = *(const uint4*)(g_centers_bf16 + goff[s] + (it + 1) * KTILE);
            }

            #pragma unroll
            for (int kk = 0; kk < 4; kk++) {
                uint32_t af[2][4], bf[2][4];
                uint32_t aaddr = abase0 + kk * 32;
                ldsm_x4(af[0], aaddr);
                ldsm_x4(af[1], aaddr + 16 * RSTRIDE);
                uint32_t baddr = bbase0 + kk * 32;
                ldsm_x4(bf[0], baddr);
                ldsm_x4(bf[1], baddr + 16 * RSTRIDE);

                #pragma unroll
                for (int mi = 0; mi < 2; mi++) {
                    #pragma unroll
                    for (int g = 0; g < 2; g++) {
                        mma16816(acc[mi][g * 2 + 0], af[mi], bf[g][0], bf[g][2]);
                        mma16816(acc[mi][g * 2 + 1], af[mi], bf[g][1], bf[g][3]);
                    }
                }
            }
            __syncthreads();
            if (it < 15) {
                #pragma unroll
                for (int s = 0; s < 6; s++)
                    *(uint4*)(s_raw + soff[s]) = stg[s];
            }
            __syncthreads();
        }

        float local = 0.f;
        int g8 = lane >> 2, tg = lane & 3;
        #pragma unroll
        for (int mi = 0; mi < 2; mi++) {
            #pragma unroll
            for (int nt = 0; nt < 4; nt++) {
                #pragma unroll
                for (int r = 0; r < 4; r++) {
                    int i = ibase + m0 + mi * 16 + g8 + ((r >> 1) * 8);
                    int j = jbase + n0 + nt * 8 + tg * 2 + (r & 1);
                    if (i < j && j < NCLASS) {
                        float d2 = g_sq[i] + g_sq[j] - 2.0f * acc[mi][nt][r];
                        float d  = sqrtf(fmaxf(d2, 0.0f));
                        local += fmaxf(1.0f - d, 0.0f);
                    }
                }
            }
        }
        local = warp_sum(local);
        float* ws = (float*)s_raw;
        __syncthreads();
        if (lane == 0) ws[wid] = local;
        __syncthreads();
        if (t == 0) {
            float tot = 0.f;
            #pragma unroll
            for (int q = 0; q < 8; q++) tot += ws[q];
            atomicAdd(&g_accum[1], tot);
        }
    }

    // -------- last-block final output + state reset for next replay --------
    __threadfence();
    __syncthreads();
    if (t == 0) {
        int d = atomicAdd(&g_done, 1);
        s_amlast = (d == (int)gridDim.x - 1);
    }
    __syncthreads();
    if (s_amlast) {
        if (t == 0) {
            float intra = g_accum[0] / (float)BATCH;
            float inter = g_accum[1] / N_PAIRS;
            out[0] = intra - 0.5f * inter;
            g_accum[0] = 0.f;
            g_accum[1] = 0.f;
            g_novf = 0;
            g_done = 0;
        }
        #pragma unroll
        for (int q = 0; q < 4; q++) g_counts[t + q * 256] = 0;
    }
}

// ---------------- launch ----------------
extern "C" void kernel_launch(void* const* d_in, const int* in_sizes, int n_in,
                              void* d_out, int out_size) {
    const float* f       = (const float*)d_in[0];
    const float* fa      = (const float*)d_in[1];
    const float* centers = (const float*)d_in[2];
    const void*  labels  = d_in[3];
    float* out = (float*)d_out;

    k_prep<<<BATCH / 256, 256>>>(labels);
    k_update<<<NCLASS, 256>>>(f, centers);
    k_fused<<<GEMM_BLOCKS + INTRA_BLOCKS, 256>>>(fa, labels, out);
}

// round 14
// speedup vs baseline: 1.1311x; 1.0537x over previous
#include <cuda_runtime.h>
#include <cuda_bf16.h>
#include <cstdint>

#define BATCH   8192
#define DIM     1024
#define NCLASS  1000
#define CPAD    1024
#define N_PAIRS 499500.0f   // 1000*999/2
#define BUCKET_CAP 64

// ---------------- scratch (device globals; zero at load) ----------------
__device__ int   g_counts[CPAD];               // zeroed by k_fused final block
__device__ int   g_bucket[NCLASS * BUCKET_CAP];
__device__ int   g_ovf[BATCH];                 // overflow (class<<16 | row)
__device__ int   g_novf;                       // zeroed by k_fused final block
__device__ int   g_lab64;                      // label width flag (set by k_prep)
__device__ float g_centers_new[CPAD * DIM];           // rows >= NCLASS stay 0
__device__ __nv_bfloat16 g_centers_bf16[CPAD * DIM];  // rows >= NCLASS stay 0
__device__ float g_sq[CPAD];                          // entries >= NCLASS stay 0
__device__ float g_accum[2];                   // zeroed by k_fused final block
__device__ int   g_done;                       // zeroed by k_fused final block

// ---------------- helpers ----------------
__device__ __forceinline__ int decode_label(const int* w, int b, int lab64) {
    int v = lab64 ? w[2 * b] : w[b];
    return (v >= 0 && v < NCLASS) ? v : 0;
}

__device__ __forceinline__ float warp_sum(float v) {
    #pragma unroll
    for (int o = 16; o; o >>= 1) v += __shfl_xor_sync(0xffffffffu, v, o);
    return v;
}

__device__ __forceinline__ void ldsm_x4(uint32_t r[4], uint32_t saddr) {
    asm volatile("ldmatrix.sync.aligned.m8n8.x4.shared.b16 {%0,%1,%2,%3}, [%4];"
                 : "=r"(r[0]), "=r"(r[1]), "=r"(r[2]), "=r"(r[3]) : "r"(saddr));
}

__device__ __forceinline__ void mma16816(float d[4], const uint32_t a[4], uint32_t b0, uint32_t b1) {
    asm volatile("mma.sync.aligned.m16n8k16.row.col.f32.bf16.bf16.f32 "
                 "{%0,%1,%2,%3},{%4,%5,%6,%7},{%8,%9},{%0,%1,%2,%3};"
                 : "+f"(d[0]), "+f"(d[1]), "+f"(d[2]), "+f"(d[3])
                 : "r"(a[0]), "r"(a[1]), "r"(a[2]), "r"(a[3]), "r"(b0), "r"(b1));
}

// ============ 1: bucket scatter — no scan, no grid barrier ============
__global__ __launch_bounds__(256) void k_prep(const void* __restrict__ labels) {
    __shared__ int s_lab64;
    int t = threadIdx.x;
    const int* w = (const int*)labels;
    if (t < 32) {
        unsigned nz = __ballot_sync(0xffffffffu, w[2 * t + 1] != 0);
        if (t == 0) {
            s_lab64 = (nz == 0u);
            if (blockIdx.x == 0) g_lab64 = s_lab64;
        }
    }
    __syncthreads();
    int lab64 = s_lab64;

    int b = blockIdx.x * 256 + t;   // 32 blocks * 256 = BATCH
    int lab = decode_label(w, b, lab64);
    int pos = atomicAdd(&g_counts[lab], 1);
    if (pos < BUCKET_CAP) {
        g_bucket[lab * BUCKET_CAP + pos] = b;
    } else {
        int o = atomicAdd(&g_novf, 1);
        if (o < BATCH) g_ovf[o] = (lab << 16) | b;
    }
}

// ============ 2: center update — warp-per-row inline norms, smem-atomic accumulate ============
__global__ __launch_bounds__(256) void k_update(const float* __restrict__ f,
                                                const float* __restrict__ centers) {
    __shared__ float s_acc[DIM];   // 4 KB class accumulator
    __shared__ float red[8];

    int c = blockIdx.x;
    int t = threadIdx.x;
    int wid = t >> 5, lane = t & 31;
    int cnt = g_counts[c];
    int inb = min(cnt, BUCKET_CAP);
    int novf = min(g_novf, BATCH);

    *(float4*)&s_acc[t * 4] = make_float4(0.f, 0.f, 0.f, 0.f);
    __syncthreads();

    for (int i = wid; i < inb; i += 8) {
        int r = g_bucket[c * BUCKET_CAP + i];
        const float4* row = (const float4*)(f + (size_t)r * DIM);
        float4 v[8];
        float ss = 0.f;
        #pragma unroll
        for (int q = 0; q < 8; q++) {
            v[q] = row[q * 32 + lane];
            ss += v[q].x * v[q].x + v[q].y * v[q].y + v[q].z * v[q].z + v[q].w * v[q].w;
        }
        ss = warp_sum(ss);
        float inv = 1.0f / fmaxf(sqrtf(ss), 1e-12f);
        #pragma unroll
        for (int q = 0; q < 8; q++) {
            float* dst = &s_acc[q * 128 + lane * 4];   // conflict-free across lanes
            atomicAdd(dst + 0, v[q].x * inv);
            atomicAdd(dst + 1, v[q].y * inv);
            atomicAdd(dst + 2, v[q].z * inv);
            atomicAdd(dst + 3, v[q].w * inv);
        }
    }
    for (int i = wid; i < novf; i += 8) {
        int e = g_ovf[i];
        if ((e >> 16) == c) {
            int r = e & 0xffff;
            const float4* row = (const float4*)(f + (size_t)r * DIM);
            float4 v[8];
            float ss = 0.f;
            #pragma unroll
            for (int q = 0; q < 8; q++) {
                v[q] = row[q * 32 + lane];
                ss += v[q].x * v[q].x + v[q].y * v[q].y + v[q].z * v[q].z + v[q].w * v[q].w;
            }
            ss = warp_sum(ss);
            float inv = 1.0f / fmaxf(sqrtf(ss), 1e-12f);
            #pragma unroll
            for (int q = 0; q < 8; q++) {
                float* dst = &s_acc[q * 128 + lane * 4];
                atomicAdd(dst + 0, v[q].x * inv);
                atomicAdd(dst + 1, v[q].y * inv);
                atomicAdd(dst + 2, v[q].z * inv);
                atomicAdd(dst + 3, v[q].w * inv);
            }
        }
    }
    __syncthreads();

    float4 sum = *(float4*)&s_acc[t * 4];
    float rc = 1.0f / fmaxf((float)cnt, 1.0f);
    float4 mean = {sum.x * rc, sum.y * rc, sum.z * rc, sum.w * rc};
    float4 co = *(const float4*)(centers + (size_t)c * DIM + t * 4);

    int zflag = (co.x == 0.f && co.y == 0.f && co.z == 0.f && co.w == 0.f);
    int allz = __syncthreads_and(zflag);

    float4 outv;
    if (cnt > 0) {
        if (allz) outv = mean;
        else {
            outv.x = 0.9f * co.x + 0.1f * mean.x;
            outv.y = 0.9f * co.y + 0.1f * mean.y;
            outv.z = 0.9f * co.z + 0.1f * mean.z;
            outv.w = 0.9f * co.w + 0.1f * mean.w;
        }
    } else outv = co;

    *(float4*)(g_centers_new + (size_t)c * DIM + t * 4) = outv;

    __nv_bfloat162 p0 = __floats2bfloat162_rn(outv.x, outv.y);
    __nv_bfloat162 p1 = __floats2bfloat162_rn(outv.z, outv.w);
    uint2 pk;
    pk.x = *(uint32_t*)&p0;
    pk.y = *(uint32_t*)&p1;
    *(uint2*)(g_centers_bf16 + (size_t)c * DIM + t * 4) = pk;

    float s = outv.x * outv.x + outv.y * outv.y + outv.z * outv.z + outv.w * outv.w;
    s = warp_sum(s);
    if ((t & 31) == 0) red[t >> 5] = s;
    __syncthreads();
    if (t == 0) {
        float tot = 0.f;
        #pragma unroll
        for (int q = 0; q < 8; q++) tot += red[q];
        g_sq[c] = tot;
    }
}

// ============ 3: fused GEMM(64x64 tiles) + intra(f/fa-split) + final/reset ============
#define GEMM_BLOCKS  136            // 16*17/2 upper-tri 64x64 tiles
#define INTRA_BLOCKS 2048           // 1024 f-blocks + 1024 fa-blocks (interleaved)
#define KTILE 64
#define RSTRIDE 144                 // 64 bf16 = 128 B + 16 B pad
#define GEMM_SMEM (128 * RSTRIDE)   // A(64 rows) + B(64 rows): 18432 B

__global__ __launch_bounds__(256, 4) void k_fused(const float* __restrict__ f,
                                                  const float* __restrict__ fa,
                                                  const void* __restrict__ labels,
                                                  float* __restrict__ out) {
    __shared__ __align__(16) char s_raw[GEMM_SMEM];
    __shared__ int s_amlast;

    int t = threadIdx.x;
    int wid = t >> 5, lane = t & 31;

    if (blockIdx.x >= GEMM_BLOCKS) {
        // -------- intra: one warp = one row of f OR fa (half staging of R11) --------
        int ib = blockIdx.x - GEMM_BLOCKS;
        int half = ib & 1;                 // 0: f, 1: fa
        int b = (ib >> 1) * 8 + wid;
        int lab64 = g_lab64;
        int lab = decode_label((const int*)labels, b, lab64);

        const float* src = half ? fa : f;
        const float4* fr = (const float4*)(src + (size_t)b * DIM);
        const float4* cr = (const float4*)(g_centers_new + (size_t)lab * DIM);

        float4 v[8];
        #pragma unroll
        for (int q = 0; q < 8; q++) v[q] = fr[q * 32 + lane];

        float dot = 0.f, ss = 0.f;
        #pragma unroll
        for (int q = 0; q < 8; q++) {
            float4 cv = cr[q * 32 + lane];
            dot += v[q].x * cv.x + v[q].y * cv.y + v[q].z * cv.z + v[q].w * cv.w;
            ss  += v[q].x * v[q].x + v[q].y * v[q].y + v[q].z * v[q].z + v[q].w * v[q].w;
        }
        dot = warp_sum(dot);
        ss  = warp_sum(ss);

        float* bsum = (float*)s_raw;
        if (t == 0) *bsum = 0.f;
        __syncthreads();
        if (lane == 0) {
            float inv = 1.0f / fmaxf(sqrtf(ss), 1e-12f);
            float sqc = g_sq[lab];
            float d = sqrtf(fmaxf(1.0f - 2.0f * dot * inv + sqc, 0.0f));
            atomicAdd(bsum, d);
        }
        __syncthreads();
        if (t == 0) atomicAdd(&g_accum[0], *bsum);
    } else {
        // -------- bf16 GEMM, 64x64 tile, K-tile 64, register staging --------
        int rem = blockIdx.x, ti = 0;
        while (rem >= 16 - ti) { rem -= 16 - ti; ti++; }
        int tj = ti + rem;
        int ibase = ti * 64, jbase = tj * 64;

        // 8 warps: 4 x 2 grid of 16x32 warp tiles
        int m0 = (wid & 3) * 16;
        int n0 = (wid >> 2) * 32;

        uint32_t sbase = (uint32_t)__cvta_generic_to_shared(s_raw);

        // staging map: 128 rows * 8 chunks = 1024 slots; slot = t + 256*s
        int goff[4], soff[4];
        #pragma unroll
        for (int s = 0; s < 4; s++) {
            int slot = t + s * 256;
            int row = slot >> 3, c16 = slot & 7;
            int grow = (row < 64) ? (ibase + row) : (jbase + row - 64);
            goff[s] = grow * DIM + c16 * 8;       // bf16 elements
            soff[s] = row * RSTRIDE + c16 * 16;   // bytes
        }

        // preload tile 0
        #pragma unroll
        for (int s = 0; s < 4; s++) {
            uint4 val = *(const uint4*)(g_centers_bf16 + goff[s]);
            *(uint4*)(s_raw + soff[s]) = val;
        }
        __syncthreads();

        float acc[4][4] = {};
        int lr = lane & 15, lc = lane >> 4;
        uint32_t abase0 = sbase + (m0 + lr) * RSTRIDE + lc * 16;
        uint32_t bbase0 = sbase + (64 + n0 + lr) * RSTRIDE + lc * 16;

        for (int it = 0; it < 16; it++) {
            uint4 stg[4];
            if (it < 15) {
                #pragma unroll
                for (int s = 0; s < 4; s++)
                    stg[s] = *(const uint4*)(g_centers_bf16 + goff[s] + (it + 1) * KTILE);
            }

            #pragma unroll
            for (int kk = 0; kk < 4; kk++) {
                uint32_t af[4], bf[2][4];
                ldsm_x4(af, abase0 + kk * 32);
                ldsm_x4(bf[0], bbase0 + kk * 32);
                ldsm_x4(bf[1], bbase0 + kk * 32 + 16 * RSTRIDE);

                #pragma unroll
                for (int g = 0; g < 2; g++) {
                    mma16816(acc[g * 2 + 0], af, bf[g][0], bf[g][2]);
                    mma16816(acc[g * 2 + 1], af, bf[g][1], bf[g][3]);
                }
            }
            __syncthreads();
            if (it < 15) {
                #pragma unroll
                for (int s = 0; s < 4; s++)
                    *(uint4*)(s_raw + soff[s]) = stg[s];
            }
            __syncthreads();
        }

        // epilogue: dist + relu reduction
        float local = 0.f;
        int g8 = lane >> 2, tg = lane & 3;
        #pragma unroll
        for (int nt = 0; nt < 4; nt++) {
            #pragma unroll
            for (int r = 0; r < 4; r++) {
                int i = ibase + m0 + g8 + ((r >> 1) * 8);
                int j = jbase + n0 + nt * 8 + tg * 2 + (r & 1);
                if (i < j && j < NCLASS) {
                    float d2 = g_sq[i] + g_sq[j] - 2.0f * acc[nt][r];
                    float d  = sqrtf(fmaxf(d2, 0.0f));
                    local += fmaxf(1.0f - d, 0.0f);
                }
            }
        }
        local = warp_sum(local);
        float* ws = (float*)s_raw;
        __syncthreads();
        if (lane == 0) ws[wid] = local;
        __syncthreads();
        if (t == 0) {
            float tot = 0.f;
            #pragma unroll
            for (int q = 0; q < 8; q++) tot += ws[q];
            atomicAdd(&g_accum[1], tot);
        }
    }

    // -------- last-block final output + state reset for next replay --------
    __threadfence();
    __syncthreads();
    if (t == 0) {
        int d = atomicAdd(&g_done, 1);
        s_amlast = (d == (int)gridDim.x - 1);
    }
    __syncthreads();
    if (s_amlast) {
        if (t == 0) {
            float intra = g_accum[0] / (float)BATCH;
            float inter = g_accum[1] / N_PAIRS;
            out[0] = intra - 0.5f * inter;
            g_accum[0] = 0.f;
            g_accum[1] = 0.f;
            g_novf = 0;
            g_done = 0;
        }
        #pragma unroll
        for (int q = 0; q < 4; q++) g_counts[t + q * 256] = 0;
    }
}

// ---------------- launch ----------------
extern "C" void kernel_launch(void* const* d_in, const int* in_sizes, int n_in,
                              void* d_out, int out_size) {
    const float* f       = (const float*)d_in[0];
    const float* fa      = (const float*)d_in[1];
    const float* centers = (const float*)d_in[2];
    const void*  labels  = d_in[3];
    float* out = (float*)d_out;

    k_prep<<<BATCH / 256, 256>>>(labels);
    k_update<<<NCLASS, 256>>>(f, centers);
    k_fused<<<GEMM_BLOCKS + INTRA_BLOCKS, 256>>>(f, fa, labels, out);
}